// round 1
// baseline (speedup 1.0000x reference)
#include <cuda_runtime.h>

#define BATCH 2048
#define NNB   64
#define MM    10
#define FEAT  40
#define RMAX  (MM + 1)

// deterministic sigma_sq: per-block partials + fixed-order reduce kernel
__device__ float g_sig_partial[BATCH * MM];

__global__ __launch_bounds__(64)
void muygps_main(const float* __restrict__ x,
                 const float* __restrict__ ls,
                 const float* __restrict__ eps,
                 const int*   __restrict__ bidx,
                 const int*   __restrict__ nidx,
                 const float* __restrict__ Y,
                 float*       __restrict__ out)
{
    const int b = blockIdx.x;
    const int i = threadIdx.x;

    __shared__ __align__(16) float sxn[NNB][FEAT];   // neighbor features
    __shared__ float spd[NNB][NNB + 1];              // pairwise distances (kept across groups)
    __shared__ float sA[NNB][NNB + 1];               // working matrix / Cholesky factor (raw)
    __shared__ float scd[NNB];                       // crosswise distances
    __shared__ float snorm[NNB];
    __shared__ int   sidx[NNB];
    __shared__ float sxb[FEAT];
    __shared__ float sdinv[NNB];                     // 1/sqrt(updated diag) per column
    __shared__ float zbuf[2][RMAX];                  // double-buffered broadcast row
    __shared__ float red[2][2 * RMAX];               // cross-warp reduction partials
    __shared__ int   s_ng;
    __shared__ float s_gls[MM], s_geps[MM];
    __shared__ int   s_gcnt[MM];
    __shared__ int   s_gmem[MM][MM];

    // ---- load query point features
    if (i < FEAT) sxb[i] = x[(size_t)bidx[b] * FEAT + i];

    // ---- group models by identical (length_scale, eps): Kp shared within a group
    if (i == 0) {
        int ng = 0;
        for (int m = 0; m < MM; m++) {
            float lm = ls[m], em = eps[m];
            int g = -1;
            for (int q = 0; q < ng; q++)
                if (s_gls[q] == lm && s_geps[q] == em) { g = q; break; }
            if (g < 0) { g = ng; ng++; s_gls[g] = lm; s_geps[g] = em; s_gcnt[g] = 0; }
            s_gmem[g][s_gcnt[g]] = m;
            s_gcnt[g]++;
        }
        s_ng = ng;
    }

    // ---- gather own neighbor row; compute norm
    float xi[FEAT];
    const int myidx = nidx[b * NNB + i];
    {
        const float* xr = x + (size_t)myidx * FEAT;
        float nrm = 0.f;
#pragma unroll
        for (int f = 0; f < FEAT; f++) {
            float v = xr[f];
            xi[f] = v;
            sxn[i][f] = v;
            nrm += v * v;
        }
        snorm[i] = nrm;
        sidx[i] = myidx;
    }
    __syncthreads();

    // ---- crosswise distance (direct form: exact 0 on identical points)
    {
        float d2 = 0.f;
#pragma unroll
        for (int f = 0; f < FEAT; f++) { float t = xi[f] - sxb[f]; d2 += t * t; }
        scd[i] = (d2 > 0.f) ? sqrtf(d2) : 0.f;
    }

    // ---- pairwise distances, row i:  d2 = |xi|^2 + |xj|^2 - 2 xi.xj
    //      exact-duplicate neighbor indices forced to d = 0 (matches reference diag/dup behavior)
    {
        const float ni = snorm[i];
        for (int j = 0; j < NNB; j++) {
            const float4* vr = reinterpret_cast<const float4*>(&sxn[j][0]);
            float dot = 0.f;
#pragma unroll
            for (int q = 0; q < FEAT / 4; q++) {
                float4 v = vr[q];
                dot += xi[4 * q + 0] * v.x;
                dot += xi[4 * q + 1] * v.y;
                dot += xi[4 * q + 2] * v.z;
                dot += xi[4 * q + 3] * v.w;
            }
            float d2 = ni + snorm[j] - 2.f * dot;
            if (sidx[j] == myidx) d2 = 0.f;
            spd[i][j] = (d2 > 0.f) ? sqrtf(d2) : 0.f;
        }
    }
    __syncthreads();

    const float* Yrow = Y + ((size_t)b * NNB + i) * MM;
    const int ng = s_ng;

    for (int g = 0; g < ng; g++) {
        const float inv_ls = 1.0f / s_gls[g];
        const float epg    = s_geps[g];
        const int   nm     = s_gcnt[g];
        const int   R      = nm + 1;          // members' Y columns + 1 shared Kcross RHS

        // ---- build Kp row (only lower triangle is consumed; matrix is exactly symmetric)
        for (int j = 0; j < NNB; j++)
            sA[i][j] = __expf(-spd[i][j] * inv_ls);
        sA[i][i] += epg;
        const float Kc = __expf(-scd[i] * inv_ls);

        // ---- RHS (compile-time register indices; runtime member index goes to memory only)
        float rr[RMAX];
#pragma unroll
        for (int r = 0; r < RMAX; r++) rr[r] = 0.f;
#pragma unroll
        for (int r = 0; r < MM; r++)
            if (r < nm) rr[r] = Yrow[s_gmem[g][r]];
#pragma unroll
        for (int r = 0; r < RMAX; r++)
            if (r == nm) rr[r] = Kc;

        __syncthreads();

        // ---- Cholesky, "raw" form: columns stay unscaled, sdinv[k] = 1/sqrt(a_kk).
        //      trailing: a_ij -= (a_ik * dinv^2) * a_jk   -> ONE barrier per step.
        for (int k = 0; k < NNB; k++) {
            if (i == k) sdinv[k] = 1.0f / sqrtf(sA[k][k]);
            __syncthreads();
            if (i > k) {
                float dv = sdinv[k];
                float t = sA[i][k] * (dv * dv);
                for (int j = k + 1; j <= i; j++)
                    sA[i][j] -= t * sA[j][k];
            }
        }
        __syncthreads();

        // ---- forward solve L z = rhs (all R RHS together; double-buffered broadcast row)
        float s[RMAX], zreg[RMAX], fr[RMAX];
#pragma unroll
        for (int r = 0; r < RMAX; r++) { s[r] = 0.f; zreg[r] = 0.f; fr[r] = 0.f; }

        for (int k = 0; k < NNB; k++) {
            if (i == k) {
                float dv = sdinv[k];
#pragma unroll
                for (int r = 0; r < RMAX; r++)
                    if (r < R) { float z = (rr[r] - s[r]) * dv; zreg[r] = z; zbuf[k & 1][r] = z; }
            }
            __syncthreads();
            if (i > k) {
                float c = sA[i][k] * sdinv[k];   // = L[i][k]
#pragma unroll
                for (int r = 0; r < RMAX; r++)
                    if (r < R) s[r] += c * zbuf[k & 1][r];
            }
        }

        // ---- backward solve L^T f = z
        const float di = sdinv[i];
#pragma unroll
        for (int r = 0; r < RMAX; r++) s[r] = 0.f;

        for (int k = NNB - 1; k >= 0; k--) {
            if (i == k) {
#pragma unroll
                for (int r = 0; r < RMAX; r++)
                    if (r < R) { float f = (zreg[r] - s[r]) * di; fr[r] = f; zbuf[k & 1][r] = f; }
            }
            __syncthreads();
            if (i < k) {
                float c = sA[k][i] * di;         // = L[k][i] scaled by own column
#pragma unroll
                for (int r = 0; r < RMAX; r++)
                    if (r < R) s[r] += c * zbuf[k & 1][r];
            }
        }

        // ---- per-thread contributions: pred/var dots and sigma partial
        float pc[RMAX], scv[RMAX];
#pragma unroll
        for (int r = 0; r < RMAX; r++) { pc[r] = Kc * fr[r]; scv[r] = rr[r] * fr[r]; }

#pragma unroll
        for (int r = 0; r < RMAX; r++) {
            float v = pc[r], w = scv[r];
#pragma unroll
            for (int off = 16; off > 0; off >>= 1) {
                v += __shfl_down_sync(0xffffffffu, v, off);
                w += __shfl_down_sync(0xffffffffu, w, off);
            }
            if ((i & 31) == 0) { red[i >> 5][r] = v; red[i >> 5][RMAX + r] = w; }
        }
        __syncthreads();

        if (i == 0) {
            float var = 1.0f - (red[0][nm] + red[1][nm]);   // variance shared across group members
            for (int r = 0; r < nm; r++) {
                int m = s_gmem[g][r];
                out[b * MM + m]              = red[0][r] + red[1][r];          // predictions
                out[BATCH * MM + b * MM + m] = var;                            // variances
                g_sig_partial[b * MM + m]    = red[0][RMAX + r] + red[1][RMAX + r];
            }
        }
        __syncthreads();   // before next group overwrites sA / zbuf / red
    }
}

__global__ void sigma_reduce(float* __restrict__ out)
{
    __shared__ float sh[256];
    const int m = blockIdx.x;
    float s = 0.f;
    for (int b = threadIdx.x; b < BATCH; b += 256)
        s += g_sig_partial[b * MM + m];
    sh[threadIdx.x] = s;
    __syncthreads();
    for (int st = 128; st > 0; st >>= 1) {
        if (threadIdx.x < st) sh[threadIdx.x] += sh[threadIdx.x + st];
        __syncthreads();
    }
    if (threadIdx.x == 0)
        out[2 * BATCH * MM + m] = sh[0] / (float)(BATCH * NNB);
}

extern "C" void kernel_launch(void* const* d_in, const int* in_sizes, int n_in,
                              void* d_out, int out_size)
{
    const float* x    = (const float*)d_in[0];
    const float* ls   = (const float*)d_in[1];
    const float* eps  = (const float*)d_in[2];
    const int*   bidx = (const int*)d_in[3];
    const int*   nidx = (const int*)d_in[4];
    const float* Y    = (const float*)d_in[5];
    float* out = (float*)d_out;

    muygps_main<<<BATCH, 64>>>(x, ls, eps, bidx, nidx, Y, out);
    sigma_reduce<<<MM, 256>>>(out);
}

// round 2
// speedup vs baseline: 2.0803x; 2.0803x over previous
#include <cuda_runtime.h>

#define BATCH 2048
#define NNB   64
#define MM    10
#define FEAT  40
#define RMAX  (MM + 1)

// deterministic sigma_sq: per-block partials + fixed-order reduce kernel
__device__ float g_sig_partial[BATCH * MM];

struct ElemSmem {
    float spd[NNB][NNB + 1];        // pairwise distances (persist across groups)
    union {
        float sxn[NNB][FEAT];       // neighbor features (phase 1)
        float sA[NNB][NNB + 1];     // raw L storage for solves (phase 2)
    } u;
    float srow[2][NNB];             // double-buffered pivot-row broadcast
    float zbuf[2][12];              // double-buffered solve broadcast (padded)
    float sdinv[NNB];               // 1/sqrt(pivot)
    float scd[NNB];
    float snorm[NNB];
    int   sidx[NNB];
    float sxb[FEAT];
    float red[2][2 * RMAX];
};

struct BlockSmem {
    ElemSmem e[2];
    float gls[MM], geps[MM];
    int   gcnt[MM];
    int   gmem[MM][MM];
    int   ng;
};

__global__ void __launch_bounds__(128)
muygps_main(const float* __restrict__ x,
            const float* __restrict__ ls,
            const float* __restrict__ eps,
            const int*   __restrict__ bidx,
            const int*   __restrict__ nidx,
            const float* __restrict__ Y,
            float*       __restrict__ out)
{
    extern __shared__ char smem_raw[];
    BlockSmem* S = reinterpret_cast<BlockSmem*>(smem_raw);
    const int tid = threadIdx.x;
    const int e   = tid >> 6;                      // element within block
    const int l   = tid & 63;                      // local lane id
    const int i   = l ^ ((blockIdx.x & 1) << 5);   // row id (parity flip balances SMSPs)
    const int b   = blockIdx.x * 2 + e;
    ElemSmem* E = &S->e[e];

    if (l < FEAT) E->sxb[l] = x[(size_t)bidx[b] * FEAT + l];

    // group models by identical (length_scale, eps): Kp shared within a group
    if (tid == 0) {
        int ng = 0;
        for (int m = 0; m < MM; m++) {
            float lm = ls[m], em = eps[m];
            int g = -1;
            for (int q = 0; q < ng; q++)
                if (S->gls[q] == lm && S->geps[q] == em) { g = q; break; }
            if (g < 0) { g = ng++; S->gls[g] = lm; S->geps[g] = em; S->gcnt[g] = 0; }
            S->gmem[g][S->gcnt[g]++] = m;
        }
        S->ng = ng;
    }

    // ---- gather own neighbor row (float4), norm
    float xi[FEAT];
    const int myidx = nidx[b * NNB + i];
    {
        const float4* xr = reinterpret_cast<const float4*>(x + (size_t)myidx * FEAT);
        float4* sx = reinterpret_cast<float4*>(E->u.sxn[i]);
        float nrm = 0.f;
#pragma unroll
        for (int q = 0; q < FEAT / 4; q++) {
            float4 v = xr[q];
            sx[q] = v;
            xi[4*q+0] = v.x; xi[4*q+1] = v.y; xi[4*q+2] = v.z; xi[4*q+3] = v.w;
            nrm += v.x*v.x + v.y*v.y + v.z*v.z + v.w*v.w;
        }
        E->snorm[i] = nrm;
        E->sidx[i]  = myidx;
    }
    __syncthreads();

    // ---- crosswise distance (direct form: exact 0 on identical points)
    {
        float d2 = 0.f;
#pragma unroll
        for (int f = 0; f < FEAT; f++) { float t = xi[f] - E->sxb[f]; d2 += t * t; }
        E->scd[i] = (d2 > 0.f) ? sqrtf(d2) : 0.f;
    }

    // ---- pairwise distances (broadcast rows, conflict-free; exactly symmetric)
    {
        const float ni = E->snorm[i];
        for (int j = 0; j < NNB; j++) {
            const float4* vr = reinterpret_cast<const float4*>(E->u.sxn[j]);
            float d0 = 0.f, d1 = 0.f, d2a = 0.f, d3 = 0.f;
#pragma unroll
            for (int q = 0; q < FEAT / 4; q++) {
                float4 v = vr[q];
                d0  += xi[4*q+0] * v.x;
                d1  += xi[4*q+1] * v.y;
                d2a += xi[4*q+2] * v.z;
                d3  += xi[4*q+3] * v.w;
            }
            float dot = (d0 + d1) + (d2a + d3);
            float dd = ni + E->snorm[j] - 2.f * dot;
            if (E->sidx[j] == myidx) dd = 0.f;
            E->spd[i][j] = (dd > 0.f) ? sqrtf(dd) : 0.f;
        }
    }
    __syncthreads();

    const float* Yrow = Y + ((size_t)b * NNB + i) * MM;
    const int ng = S->ng;

    for (int g = 0; g < ng; g++) {
        const float inv_ls = 1.0f / S->gls[g];
        const float epg    = S->geps[g];
        const int   nm     = S->gcnt[g];
        const int   R      = nm + 1;

        // ---- build register-resident row of Kp
        float a[NNB];
#pragma unroll
        for (int j = 0; j < NNB; j++) {
            float v = __expf(-E->spd[i][j] * inv_ls);
            a[j] = (j == i) ? v + epg : v;
        }
        const float Kc = __expf(-E->scd[i] * inv_ls);

        // ---- RHS (compile-time register indices)
        float rr[RMAX];
#pragma unroll
        for (int r = 0; r < RMAX; r++) rr[r] = 0.f;
#pragma unroll
        for (int r = 0; r < MM; r++)
            if (r < nm) rr[r] = Yrow[S->gmem[g][r]];
#pragma unroll
        for (int r = 0; r < RMAX; r++)
            if (r == nm) rr[r] = Kc;

        float4* srow4a = reinterpret_cast<float4*>(E->srow[0]);
        float4* srow4b = reinterpret_cast<float4*>(E->srow[1]);

        // ---- bootstrap: row-0 thread publishes its row (elem 0 zeroed)
        if (i == 0) {
            E->sdinv[0] = rsqrtf(a[0]);
#pragma unroll
            for (int c = 0; c < 16; c++) {
                float4 v;
                v.x = (4*c+0 > 0) ? a[4*c+0] : 0.f;
                v.y = a[4*c+1]; v.z = a[4*c+2]; v.w = a[4*c+3];
                srow4a[c] = v;
            }
        }

        // ---- register Cholesky, fully unrolled; one barrier per step.
        //      Next pivot thread publishes its freshly-updated row into the
        //      other buffer (zero-masked below the diagonal) -> no serial publish.
#pragma unroll
        for (int k = 0; k < NNB - 1; k++) {
            __syncthreads();
            float4* rb = (k & 1) ? srow4b : srow4a;
            float4* wb = (k & 1) ? srow4a : srow4b;
            const int c0 = (k + 1) >> 2;
            if (i > k) {
                float dv = E->sdinv[k];
                float t = a[k] * dv * dv;
#pragma unroll
                for (int c = 0; c < 16; c++) {
                    if (c >= c0) {
                        float4 v = rb[c];
                        a[4*c+0] -= t * v.x;
                        a[4*c+1] -= t * v.y;
                        a[4*c+2] -= t * v.z;
                        a[4*c+3] -= t * v.w;
                    }
                }
            }
            if (i == k + 1) {
                E->sdinv[k+1] = rsqrtf(a[k+1]);
                if (k + 1 < NNB - 1) {
                    const int c1 = (k + 2) >> 2;
#pragma unroll
                    for (int c = 0; c < 16; c++) {
                        if (c >= c1) {
                            float4 v;
                            v.x = (4*c+0 > k+1) ? a[4*c+0] : 0.f;
                            v.y = (4*c+1 > k+1) ? a[4*c+1] : 0.f;
                            v.z = (4*c+2 > k+1) ? a[4*c+2] : 0.f;
                            v.w = (4*c+3 > k+1) ? a[4*c+3] : 0.f;
                            wb[c] = v;
                        }
                    }
                }
            }
        }

        // ---- dump raw L rows to smem for the solves (upper junk never read)
#pragma unroll
        for (int j = 0; j < NNB; j++) E->u.sA[i][j] = a[j];
        __syncthreads();

        const float di = E->sdinv[i];

        // ---- forward solve L z = rhs (all R RHS together)
        float s[RMAX], zreg[RMAX], fr[RMAX];
#pragma unroll
        for (int r = 0; r < RMAX; r++) { s[r] = 0.f; zreg[r] = 0.f; fr[r] = 0.f; }

        for (int k = 0; k < NNB; k++) {
            if (i == k) {
#pragma unroll
                for (int r = 0; r < RMAX; r++)
                    if (r < R) { float z = (rr[r] - s[r]) * di; zreg[r] = z; E->zbuf[k&1][r] = z; }
            }
            __syncthreads();
            if (i > k) {
                float c = E->u.sA[i][k] * E->sdinv[k];
#pragma unroll
                for (int r = 0; r < RMAX; r++)
                    if (r < R) s[r] += c * E->zbuf[k&1][r];
            }
        }

        // ---- backward solve L^T f = z
#pragma unroll
        for (int r = 0; r < RMAX; r++) s[r] = 0.f;

        for (int k = NNB - 1; k >= 0; k--) {
            if (i == k) {
#pragma unroll
                for (int r = 0; r < RMAX; r++)
                    if (r < R) { float f = (zreg[r] - s[r]) * di; fr[r] = f; E->zbuf[k&1][r] = f; }
            }
            __syncthreads();
            if (i < k) {
                float c = E->u.sA[k][i] * di;
#pragma unroll
                for (int r = 0; r < RMAX; r++)
                    if (r < R) s[r] += c * E->zbuf[k&1][r];
            }
        }

        // ---- reductions: predictions / variance / sigma partials
        float pc[RMAX], scv[RMAX];
#pragma unroll
        for (int r = 0; r < RMAX; r++) { pc[r] = Kc * fr[r]; scv[r] = rr[r] * fr[r]; }

#pragma unroll
        for (int r = 0; r < RMAX; r++) {
            float v = pc[r], w = scv[r];
#pragma unroll
            for (int off = 16; off > 0; off >>= 1) {
                v += __shfl_down_sync(0xffffffffu, v, off);
                w += __shfl_down_sync(0xffffffffu, w, off);
            }
            if ((l & 31) == 0) { E->red[l >> 5][r] = v; E->red[l >> 5][RMAX + r] = w; }
        }
        __syncthreads();

        if (i == 0) {
            float var = 1.0f - (E->red[0][nm] + E->red[1][nm]);
            for (int r = 0; r < nm; r++) {
                int m = S->gmem[g][r];
                out[b * MM + m]              = E->red[0][r] + E->red[1][r];
                out[BATCH * MM + b * MM + m] = var;
                g_sig_partial[b * MM + m]    = E->red[0][RMAX + r] + E->red[1][RMAX + r];
            }
        }
        __syncthreads();   // protect sA/srow/zbuf/red before next group
    }
}

__global__ void sigma_reduce(float* __restrict__ out)
{
    __shared__ float sh[256];
    const int m = blockIdx.x;
    float s = 0.f;
    for (int b = threadIdx.x; b < BATCH; b += 256)
        s += g_sig_partial[b * MM + m];
    sh[threadIdx.x] = s;
    __syncthreads();
    for (int st = 128; st > 0; st >>= 1) {
        if (threadIdx.x < st) sh[threadIdx.x] += sh[threadIdx.x + st];
        __syncthreads();
    }
    if (threadIdx.x == 0)
        out[2 * BATCH * MM + m] = sh[0] / (float)(BATCH * NNB);
}

extern "C" void kernel_launch(void* const* d_in, const int* in_sizes, int n_in,
                              void* d_out, int out_size)
{
    const float* x    = (const float*)d_in[0];
    const float* ls   = (const float*)d_in[1];
    const float* eps  = (const float*)d_in[2];
    const int*   bidx = (const int*)d_in[3];
    const int*   nidx = (const int*)d_in[4];
    const float* Y    = (const float*)d_in[5];
    float* out = (float*)d_out;

    cudaFuncSetAttribute(muygps_main, cudaFuncAttributeMaxDynamicSharedMemorySize,
                         (int)sizeof(BlockSmem));
    muygps_main<<<BATCH / 2, 128, sizeof(BlockSmem)>>>(x, ls, eps, bidx, nidx, Y, out);
    sigma_reduce<<<MM, 256>>>(out);
}

// round 3
// speedup vs baseline: 2.1090x; 1.0138x over previous
#include <cuda_runtime.h>

#define BATCH 2048
#define NNB   64
#define MM    10
#define FEAT  40
#define RMAX  (MM + 1)      // max rhs columns (models + 1 Kcross)
#define RPAD  12            // padded rhs register array

__device__ float g_sig_partial[MM * BATCH];

struct __align__(16) ElemSmem {
    float srow[2][80];           // pivot broadcast: 64 row + 12 rhs + pad (16B aligned)
    float sxn[NNB][FEAT];        // neighbor features (kept alive for rebuilds)
    float spdA[NNB][NNB + 1];    // distances, then raw L after factorization
    float zs[NNB][RMAX];         // forward-solve result z
    float sYo[NNB][RMAX];        // original rhs values (for sigma)
    float sdinv[NNB];            // 1/sqrt(pivot)
    float scd[NNB];
    float snorm[NNB];
    float sKc[NNB];
    int   sidx[NNB];
    float sxb[FEAT];
};

struct BlockSmem {
    ElemSmem e[2];
    float gls[MM], geps[MM];
    int   gcnt[MM];
    int   gmem[MM][MM];
    int   ng;
};

__device__ __forceinline__ void compute_distances(ElemSmem* E, const float* xi,
                                                  int i, int myidx)
{
    const float ni = E->snorm[i];
    for (int j = 0; j < NNB; j++) {
        const float4* vr = reinterpret_cast<const float4*>(E->sxn[j]);
        float d0 = 0.f, d1 = 0.f, d2 = 0.f, d3 = 0.f;
#pragma unroll
        for (int q = 0; q < FEAT / 4; q++) {
            float4 v = vr[q];
            d0 += xi[4*q+0] * v.x;
            d1 += xi[4*q+1] * v.y;
            d2 += xi[4*q+2] * v.z;
            d3 += xi[4*q+3] * v.w;
        }
        float dot = (d0 + d1) + (d2 + d3);
        float dd = ni + E->snorm[j] - 2.f * dot;
        if (E->sidx[j] == myidx) dd = 0.f;
        E->spdA[i][j] = (dd > 0.f) ? sqrtf(dd) : 0.f;
    }
}

__global__ void __launch_bounds__(128, 3)
muygps_main(const float* __restrict__ x,
            const float* __restrict__ ls,
            const float* __restrict__ eps,
            const int*   __restrict__ bidx,
            const int*   __restrict__ nidx,
            const float* __restrict__ Y,
            float*       __restrict__ out)
{
    extern __shared__ char smem_raw[];
    BlockSmem* S = reinterpret_cast<BlockSmem*>(smem_raw);
    const int tid = threadIdx.x;
    const int e   = tid >> 6;
    const int i   = tid & 63;
    const int b   = blockIdx.x * 2 + e;
    ElemSmem* E = &S->e[e];

    if (i < FEAT) E->sxb[i] = x[(size_t)bidx[b] * FEAT + i];

    // group models by identical (length_scale, eps): Kp shared within group
    if (tid == 0) {
        int ng = 0;
        for (int m = 0; m < MM; m++) {
            float lm = ls[m], em = eps[m];
            int g = -1;
            for (int q = 0; q < ng; q++)
                if (S->gls[q] == lm && S->geps[q] == em) { g = q; break; }
            if (g < 0) { g = ng++; S->gls[g] = lm; S->geps[g] = em; S->gcnt[g] = 0; }
            S->gmem[g][S->gcnt[g]++] = m;
        }
        S->ng = ng;
    }

    // ---- gather neighbor features, norm
    float xi[FEAT];
    const int myidx = nidx[b * NNB + i];
    {
        const float4* xr = reinterpret_cast<const float4*>(x + (size_t)myidx * FEAT);
        float4* sx = reinterpret_cast<float4*>(E->sxn[i]);
        float nrm = 0.f;
#pragma unroll
        for (int q = 0; q < FEAT / 4; q++) {
            float4 v = xr[q];
            sx[q] = v;
            xi[4*q+0] = v.x; xi[4*q+1] = v.y; xi[4*q+2] = v.z; xi[4*q+3] = v.w;
            nrm += v.x*v.x + v.y*v.y + v.z*v.z + v.w*v.w;
        }
        E->snorm[i] = nrm;
        E->sidx[i]  = myidx;
    }
    __syncthreads();

    // ---- crosswise distance (direct diff: exact 0 on identical points)
    {
        float d2 = 0.f;
#pragma unroll
        for (int f = 0; f < FEAT; f++) { float t = xi[f] - E->sxb[f]; d2 += t * t; }
        E->scd[i] = (d2 > 0.f) ? sqrtf(d2) : 0.f;
    }

    compute_distances(E, xi, i, myidx);
    __syncthreads();

    const float* Yrow = Y + ((size_t)b * NNB + i) * MM;
    const int ng = S->ng;

    float4* s4a = reinterpret_cast<float4*>(E->srow[0]);
    float4* s4b = reinterpret_cast<float4*>(E->srow[1]);

    for (int g = 0; g < ng; g++) {
        if (g > 0) {                       // spdA was overwritten by L; rebuild
            compute_distances(E, xi, i, myidx);
            __syncthreads();
        }
        const float inv_ls = 1.0f / S->gls[g];
        const float epg    = S->geps[g];
        const int   nm     = S->gcnt[g];
        const int   R      = nm + 1;

        // ---- build register row of Kp
        float a[NNB];
#pragma unroll
        for (int j = 0; j < NNB; j++) {
            float v = __expf(-E->spdA[i][j] * inv_ls);
            a[j] = (j == i) ? v + epg : v;
        }
        const float Kc = __expf(-E->scd[i] * inv_ls);
        E->sKc[i] = Kc;

        // ---- rhs registers (models' Y columns + Kcross), padded to 12
        float rr[RPAD];
#pragma unroll
        for (int r = 0; r < RPAD; r++) rr[r] = 0.f;
#pragma unroll
        for (int r = 0; r < MM; r++)
            if (r < nm) rr[r] = Yrow[S->gmem[g][r]];
#pragma unroll
        for (int r = 0; r < RMAX; r++)
            if (r == nm) rr[r] = Kc;
#pragma unroll
        for (int r = 0; r < RMAX; r++) E->sYo[i][r] = rr[r];

        // ---- bootstrap publish (row 0 + rhs), zero-masked at j==0
        if (i == 0) {
            E->sdinv[0] = rsqrtf(a[0]);
#pragma unroll
            for (int c = 0; c < 16; c++) {
                float4 v;
                v.x = (4*c+0 > 0) ? a[4*c+0] : 0.f;
                v.y = a[4*c+1]; v.z = a[4*c+2]; v.w = a[4*c+3];
                s4a[c] = v;
            }
#pragma unroll
            for (int c = 0; c < 3; c++) {
                float4 v = make_float4(rr[4*c+0], rr[4*c+1], rr[4*c+2], rr[4*c+3]);
                s4a[16 + c] = v;
            }
        }

        // ---- Cholesky with FUSED forward solve: one barrier per step.
#pragma unroll
        for (int k = 0; k < NNB - 1; k++) {
            __syncthreads();
            const float4* rb = (k & 1) ? s4b : s4a;
            float4*       wb = (k & 1) ? s4a : s4b;
            const int c0 = (k + 1) >> 2;
            if (i > k) {
                float dv = E->sdinv[k];
                float t = a[k] * dv * dv;
#pragma unroll
                for (int c = c0; c < 16; c++) {
                    float4 v = rb[c];
                    a[4*c+0] -= t * v.x;
                    a[4*c+1] -= t * v.y;
                    a[4*c+2] -= t * v.z;
                    a[4*c+3] -= t * v.w;
                }
#pragma unroll
                for (int c = 0; c < 3; c++) {
                    float4 v = rb[16 + c];
                    rr[4*c+0] -= t * v.x;
                    rr[4*c+1] -= t * v.y;
                    rr[4*c+2] -= t * v.z;
                    rr[4*c+3] -= t * v.w;
                }
            }
            if (i == k + 1) {
                E->sdinv[k+1] = rsqrtf(a[k+1]);
                if (k + 1 < NNB - 1) {
                    const int c1 = (k + 2) >> 2;
#pragma unroll
                    for (int c = c1; c < 16; c++) {
                        float4 v;
                        v.x = (4*c+0 > k+1) ? a[4*c+0] : 0.f;
                        v.y = (4*c+1 > k+1) ? a[4*c+1] : 0.f;
                        v.z = (4*c+2 > k+1) ? a[4*c+2] : 0.f;
                        v.w = (4*c+3 > k+1) ? a[4*c+3] : 0.f;
                        wb[c] = v;
                    }
#pragma unroll
                    for (int c = 0; c < 3; c++)
                        wb[16 + c] = make_float4(rr[4*c+0], rr[4*c+1], rr[4*c+2], rr[4*c+3]);
                }
            }
        }

        // ---- dump raw L and z = fwd-solve result; one barrier
#pragma unroll
        for (int j = 0; j < NNB; j++) E->spdA[i][j] = a[j];
        {
            float dvi = E->sdinv[i];
#pragma unroll
            for (int r = 0; r < RMAX; r++) E->zs[i][r] = rr[r] * dvi;
        }
        __syncthreads();

        // ---- warp-local backward solve (L^T f = z), RHS split across 2 warps,
        //      2 rows per lane, fully unrolled shuffle chain, ZERO barriers.
        {
            const int wsub  = (tid >> 5) & 1;
            const int lane  = tid & 31;
            const int RHs   = (R + 1) >> 1;
            const int rbase = wsub ? RHs : 0;
            const int rend  = wsub ? R   : RHs;

            float accL[6], accH[6], pred[6], sig[6], fk[6];
#pragma unroll
            for (int r = 0; r < 6; r++) { accL[r] = 0.f; accH[r] = 0.f; pred[r] = 0.f; sig[r] = 0.f; }

#pragma unroll
            for (int kk = 0; kk < NNB; kk++) {
                const int k = NNB - 1 - kk;
                const float dv = E->sdinv[k];
#pragma unroll
                for (int r = 0; r < 6; r++) {
                    int rq = rbase + r; if (rq >= RMAX) rq = 0;
                    float accv = (k >= 32) ? accH[r] : accL[r];
                    fk[r] = (E->zs[k][rq] - dv * accv) * dv;
                }
#pragma unroll
                for (int r = 0; r < 6; r++)
                    fk[r] = __shfl_sync(0xffffffffu, fk[r], k & 31);

                float rowL = E->spdA[k][lane];
                if (lane < k) {
#pragma unroll
                    for (int r = 0; r < 6; r++) accL[r] += rowL * fk[r];
                }
                if (k > 32) {
                    float rowH = E->spdA[k][lane + 32];
                    if (lane + 32 < k) {
#pragma unroll
                        for (int r = 0; r < 6; r++) accH[r] += rowH * fk[r];
                    }
                }
                if (lane == 0) {
                    float kc = E->sKc[k];
#pragma unroll
                    for (int r = 0; r < 6; r++) {
                        int rq = rbase + r; if (rq >= RMAX) rq = 0;
                        pred[r] += kc * fk[r];
                        sig[r]  += E->sYo[k][rq] * fk[r];
                    }
                }
            }

            if (lane == 0) {
#pragma unroll
                for (int r = 0; r < 6; r++) {
                    int rg = rbase + r;
                    if (rg < rend) {
                        if (rg < nm) {
                            int m = S->gmem[g][rg];
                            out[b * MM + m]            = pred[r];
                            g_sig_partial[m * BATCH + b] = sig[r];
                        } else {       // rg == nm -> shared variance column
                            float var = 1.0f - pred[r];
                            for (int q = 0; q < nm; q++)
                                out[BATCH * MM + b * MM + S->gmem[g][q]] = var;
                        }
                    }
                }
            }
        }
        __syncthreads();   // protect smem before next group
    }
}

__global__ void sigma_reduce(float* __restrict__ out)
{
    __shared__ float sh[256];
    const int m = blockIdx.x;
    float s = 0.f;
    for (int t = threadIdx.x; t < BATCH; t += 256)
        s += g_sig_partial[m * BATCH + t];           // coalesced
    sh[threadIdx.x] = s;
    __syncthreads();
    for (int st = 128; st > 0; st >>= 1) {
        if (threadIdx.x < st) sh[threadIdx.x] += sh[threadIdx.x + st];
        __syncthreads();
    }
    if (threadIdx.x == 0)
        out[2 * BATCH * MM + m] = sh[0] / (float)(BATCH * NNB);
}

// no-op pads so that ncu's "-s 5" (launch index 5 = 1 mod 4) lands on muygps_main
__global__ void _prof_pad_a() {}
__global__ void _prof_pad_b() {}

extern "C" void kernel_launch(void* const* d_in, const int* in_sizes, int n_in,
                              void* d_out, int out_size)
{
    const float* x    = (const float*)d_in[0];
    const float* ls   = (const float*)d_in[1];
    const float* eps  = (const float*)d_in[2];
    const int*   bidx = (const int*)d_in[3];
    const int*   nidx = (const int*)d_in[4];
    const float* Y    = (const float*)d_in[5];
    float* out = (float*)d_out;

    cudaFuncSetAttribute(muygps_main, cudaFuncAttributeMaxDynamicSharedMemorySize,
                         (int)sizeof(BlockSmem));
    _prof_pad_a<<<1, 1>>>();
    muygps_main<<<BATCH / 2, 128, sizeof(BlockSmem)>>>(x, ls, eps, bidx, nidx, Y, out);
    _prof_pad_b<<<1, 1>>>();
    sigma_reduce<<<MM, 256>>>(out);
}

// round 4
// speedup vs baseline: 2.1629x; 1.0256x over previous
#include <cuda_runtime.h>

#define BATCH 2048
#define NNB   64
#define MM    10
#define FEAT  40
#define RMAX  (MM + 1)      // max rhs columns (models + 1 Kcross)
#define RPAD  12

__device__ float g_sig_partial[MM * BATCH];
__device__ unsigned int g_done = 0;

// per-element named barrier: 64 threads (2 warps), ids 1,2
#define EBAR(id) asm volatile("bar.sync %0, 64;" :: "r"(id) : "memory")

struct __align__(16) ElemSmem {
    float spdA[NNB][NNB + 1];        // distances, then raw L
    union {
        float sxn[NNB][FEAT];        // phase 1: neighbor features
        struct {
            float zs[NNB][RPAD];     // forward-solve result
            float sYo[NNB][RPAD];    // original rhs (for sigma)
            float srow[2][80];       // pivot broadcast: 64 row + 12 rhs + dv2 + pad
        } p2;
    } u;
    float sdinv[NNB];
    float scd[NNB];
    float snorm[NNB];
    float sKc[NNB];
    int   sidx[NNB];
    float sxb[FEAT];
};

struct BlockSmem {
    ElemSmem e[2];
    float gls[MM], geps[MM];
    int   gcnt[MM];
    int   gmem[MM][MM];
    int   ng;
    unsigned int ticket;
    float sred[4];
};

// recompute pairwise distances from sxn (used in phase 1 and ng>1 rebuild)
__device__ __forceinline__ void dist_from_sxn(ElemSmem* E, const float* xi,
                                              int i, int myidx)
{
    const float ni = E->snorm[i];
    for (int j = 0; j < NNB; j++) {
        const float4* vr = reinterpret_cast<const float4*>(E->u.sxn[j]);
        float d0 = 0.f, d1 = 0.f, d2 = 0.f, d3 = 0.f;
#pragma unroll
        for (int q = 0; q < FEAT / 4; q++) {
            float4 v = vr[q];
            d0 += xi[4*q+0] * v.x;
            d1 += xi[4*q+1] * v.y;
            d2 += xi[4*q+2] * v.z;
            d3 += xi[4*q+3] * v.w;
        }
        float dot = (d0 + d1) + (d2 + d3);
        float dd = ni + E->snorm[j] - 2.f * dot;
        if (E->sidx[j] == myidx) dd = 0.f;
        E->spdA[i][j] = (dd > 0.f) ? sqrtf(dd) : 0.f;
    }
}

__global__ void __launch_bounds__(128, 3)
muygps_main(const float* __restrict__ x,
            const float* __restrict__ ls,
            const float* __restrict__ eps,
            const int*   __restrict__ bidx,
            const int*   __restrict__ nidx,
            const float* __restrict__ Y,
            float*       __restrict__ out)
{
    extern __shared__ char smem_raw[];
    BlockSmem* S = reinterpret_cast<BlockSmem*>(smem_raw);
    const int tid  = threadIdx.x;
    const int e    = tid >> 6;
    const int i    = tid & 63;
    const int barid = 1 + e;
    const int b    = blockIdx.x * 2 + e;
    ElemSmem* E = &S->e[e];

    if (i < FEAT) E->sxb[i] = x[(size_t)bidx[b] * FEAT + i];

    if (tid == 0) {
        int ng = 0;
        for (int m = 0; m < MM; m++) {
            float lm = ls[m], em = eps[m];
            int g = -1;
            for (int q = 0; q < ng; q++)
                if (S->gls[q] == lm && S->geps[q] == em) { g = q; break; }
            if (g < 0) { g = ng++; S->gls[g] = lm; S->geps[g] = em; S->gcnt[g] = 0; }
            S->gmem[g][S->gcnt[g]++] = m;
        }
        S->ng = ng;
    }

    const int myidx = nidx[b * NNB + i];

    // ---- phase 1: gather features, norms, distances (xi scoped => dies after)
    {
        float xi[FEAT];
        const float4* xr = reinterpret_cast<const float4*>(x + (size_t)myidx * FEAT);
        float4* sx = reinterpret_cast<float4*>(E->u.sxn[i]);
        float nrm = 0.f;
#pragma unroll
        for (int q = 0; q < FEAT / 4; q++) {
            float4 v = xr[q];
            sx[q] = v;
            xi[4*q+0] = v.x; xi[4*q+1] = v.y; xi[4*q+2] = v.z; xi[4*q+3] = v.w;
            nrm += v.x*v.x + v.y*v.y + v.z*v.z + v.w*v.w;
        }
        E->snorm[i] = nrm;
        E->sidx[i]  = myidx;
        __syncthreads();                 // covers group table + both elements

        float d2 = 0.f;
#pragma unroll
        for (int f = 0; f < FEAT; f++) { float t = xi[f] - E->sxb[f]; d2 += t * t; }
        E->scd[i] = (d2 > 0.f) ? sqrtf(d2) : 0.f;

        dist_from_sxn(E, xi, i, myidx);
    }
    EBAR(barid);

    const float* Yrow = Y + ((size_t)b * NNB + i) * MM;
    const int ng = S->ng;

    for (int g = 0; g < ng; g++) {
        if (g > 0) {   // general case: re-gather features (union was overwritten), rebuild
            float xi[FEAT];
            const float4* xr = reinterpret_cast<const float4*>(x + (size_t)myidx * FEAT);
            float4* sx = reinterpret_cast<float4*>(E->u.sxn[i]);
#pragma unroll
            for (int q = 0; q < FEAT / 4; q++) {
                float4 v = xr[q];
                sx[q] = v;
                xi[4*q+0] = v.x; xi[4*q+1] = v.y; xi[4*q+2] = v.z; xi[4*q+3] = v.w;
            }
            EBAR(barid);
            dist_from_sxn(E, xi, i, myidx);
            EBAR(barid);
        }
        const float inv_ls = 1.0f / S->gls[g];
        const float epg    = S->geps[g];
        const int   nm     = S->gcnt[g];
        const int   R      = nm + 1;

        float4* s4a = reinterpret_cast<float4*>(E->u.p2.srow[0]);
        float4* s4b = reinterpret_cast<float4*>(E->u.p2.srow[1]);

        // ---- register row of Kp
        float a[NNB];
#pragma unroll
        for (int j = 0; j < NNB; j++) {
            float v = __expf(-E->spdA[i][j] * inv_ls);
            a[j] = (j == i) ? v + epg : v;
        }
        const float Kc = __expf(-E->scd[i] * inv_ls);
        E->sKc[i] = Kc;

        // ---- rhs registers
        float rr[RPAD];
#pragma unroll
        for (int r = 0; r < RPAD; r++) rr[r] = 0.f;
#pragma unroll
        for (int r = 0; r < MM; r++)
            if (r < nm) rr[r] = Yrow[S->gmem[g][r]];
#pragma unroll
        for (int r = 0; r < RMAX; r++)
            if (r == nm) rr[r] = Kc;
#pragma unroll
        for (int r = 0; r < RMAX; r++) E->u.p2.sYo[i][r] = rr[r];

        // ---- bootstrap publish (row 0 + rhs + dv2)
        if (i == 0) {
            float dv = rsqrtf(a[0]);
            E->sdinv[0] = dv;
#pragma unroll
            for (int c = 0; c < 16; c++) {
                float4 v;
                v.x = (4*c+0 > 0) ? a[4*c+0] : 0.f;
                v.y = a[4*c+1]; v.z = a[4*c+2]; v.w = a[4*c+3];
                s4a[c] = v;
            }
#pragma unroll
            for (int c = 0; c < 3; c++)
                s4a[16 + c] = make_float4(rr[4*c+0], rr[4*c+1], rr[4*c+2], rr[4*c+3]);
            s4a[19] = make_float4(dv * dv, 0.f, 0.f, 0.f);
        }

        // ---- Cholesky + fused forward solve; one NAMED barrier per step
#pragma unroll
        for (int k = 0; k < NNB - 1; k++) {
            EBAR(barid);
            const float4* rb = (k & 1) ? s4b : s4a;
            float4*       wb = (k & 1) ? s4a : s4b;
            const int c0 = (k + 1) >> 2;
            if (i > k) {
                float t = a[k] * rb[19].x;       // a[k] * dv^2
#pragma unroll
                for (int c = c0; c < 16; c++) {
                    float4 v = rb[c];
                    a[4*c+0] -= t * v.x;
                    a[4*c+1] -= t * v.y;
                    a[4*c+2] -= t * v.z;
                    a[4*c+3] -= t * v.w;
                }
#pragma unroll
                for (int c = 0; c < 3; c++) {
                    float4 v = rb[16 + c];
                    rr[4*c+0] -= t * v.x;
                    rr[4*c+1] -= t * v.y;
                    rr[4*c+2] -= t * v.z;
                    rr[4*c+3] -= t * v.w;
                }
            }
            if (i == k + 1) {
                float dv = rsqrtf(a[k+1]);
                E->sdinv[k+1] = dv;
                if (k + 1 < NNB - 1) {
                    const int c1 = (k + 2) >> 2;
#pragma unroll
                    for (int c = c1; c < 16; c++) {
                        float4 v;
                        v.x = (4*c+0 > k+1) ? a[4*c+0] : 0.f;
                        v.y = (4*c+1 > k+1) ? a[4*c+1] : 0.f;
                        v.z = (4*c+2 > k+1) ? a[4*c+2] : 0.f;
                        v.w = (4*c+3 > k+1) ? a[4*c+3] : 0.f;
                        wb[c] = v;
                    }
#pragma unroll
                    for (int c = 0; c < 3; c++)
                        wb[16 + c] = make_float4(rr[4*c+0], rr[4*c+1], rr[4*c+2], rr[4*c+3]);
                    wb[19] = make_float4(dv * dv, 0.f, 0.f, 0.f);
                }
            }
        }

        // ---- dump raw L rows; store z (forward result)
#pragma unroll
        for (int j = 0; j < NNB; j++) E->spdA[i][j] = a[j];
        {
            float dvi = E->sdinv[i];
#pragma unroll
            for (int r = 0; r < RMAX; r++) E->u.p2.zs[i][r] = rr[r] * dvi;
        }
        EBAR(barid);

        // ---- warp-local backward solve (zero barriers), RHS split across 2 warps
        {
            const int wsub  = (tid >> 5) & 1;
            const int lane  = tid & 31;
            const int RHs   = (R + 1) >> 1;
            const int rbase = wsub ? RHs : 0;
            const int rend  = wsub ? R   : RHs;

            float accL[6], accH[6], pred[6], sig[6], fk[6];
#pragma unroll
            for (int r = 0; r < 6; r++) { accL[r]=0.f; accH[r]=0.f; pred[r]=0.f; sig[r]=0.f; }

#pragma unroll
            for (int kk = 0; kk < NNB; kk++) {
                const int k = NNB - 1 - kk;
                const float dv = E->sdinv[k];
#pragma unroll
                for (int r = 0; r < 6; r++) {
                    int rq = rbase + r; if (rq >= RMAX) rq = 0;
                    float accv = (k >= 32) ? accH[r] : accL[r];
                    fk[r] = (E->u.p2.zs[k][rq] - dv * accv) * dv;
                }
#pragma unroll
                for (int r = 0; r < 6; r++)
                    fk[r] = __shfl_sync(0xffffffffu, fk[r], k & 31);

                float rowL = E->spdA[k][lane];
                if (lane < k) {
#pragma unroll
                    for (int r = 0; r < 6; r++) accL[r] += rowL * fk[r];
                }
                if (k > 32) {
                    float rowH = E->spdA[k][lane + 32];
                    if (lane + 32 < k) {
#pragma unroll
                        for (int r = 0; r < 6; r++) accH[r] += rowH * fk[r];
                    }
                }
                if (lane == 0) {
                    float kc = E->sKc[k];
#pragma unroll
                    for (int r = 0; r < 6; r++) {
                        int rq = rbase + r; if (rq >= RMAX) rq = 0;
                        pred[r] += kc * fk[r];
                        sig[r]  += E->u.p2.sYo[k][rq] * fk[r];
                    }
                }
            }

            if (lane == 0) {
#pragma unroll
                for (int r = 0; r < 6; r++) {
                    int rg = rbase + r;
                    if (rg < rend) {
                        if (rg < nm) {
                            int m = S->gmem[g][rg];
                            out[b * MM + m]              = pred[r];
                            g_sig_partial[m * BATCH + b] = sig[r];
                        } else {
                            float var = 1.0f - pred[r];
                            for (int q = 0; q < nm; q++)
                                out[BATCH * MM + b * MM + S->gmem[g][q]] = var;
                        }
                    }
                }
            }
        }
        EBAR(barid);
    }

    // ---- last-block sigma reduction (deterministic fixed-order sum)
    __threadfence();
    __syncthreads();
    if (tid == 0) S->ticket = atomicAdd(&g_done, 1u);
    __syncthreads();
    if (S->ticket == gridDim.x - 1) {
        __threadfence();
        const int lane = tid & 31, w = tid >> 5;
        for (int m = 0; m < MM; m++) {
            float s = 0.f;
            for (int t = tid; t < BATCH; t += 128)
                s += g_sig_partial[m * BATCH + t];
#pragma unroll
            for (int off = 16; off > 0; off >>= 1)
                s += __shfl_down_sync(0xffffffffu, s, off);
            if (lane == 0) S->sred[w] = s;
            __syncthreads();
            if (tid == 0) {
                float tot = S->sred[0] + S->sred[1] + S->sred[2] + S->sred[3];
                out[2 * BATCH * MM + m] = tot / (float)(BATCH * NNB);
            }
            __syncthreads();
        }
        if (tid == 0) g_done = 0;        // reset for next graph replay
    }
}

extern "C" void kernel_launch(void* const* d_in, const int* in_sizes, int n_in,
                              void* d_out, int out_size)
{
    const float* x    = (const float*)d_in[0];
    const float* ls   = (const float*)d_in[1];
    const float* eps  = (const float*)d_in[2];
    const int*   bidx = (const int*)d_in[3];
    const int*   nidx = (const int*)d_in[4];
    const float* Y    = (const float*)d_in[5];
    float* out = (float*)d_out;

    cudaFuncSetAttribute(muygps_main, cudaFuncAttributeMaxDynamicSharedMemorySize,
                         (int)sizeof(BlockSmem));
    muygps_main<<<BATCH / 2, 128, sizeof(BlockSmem)>>>(x, ls, eps, bidx, nidx, Y, out);
}